// round 12
// baseline (speedup 1.0000x reference)
#include <cuda_runtime.h>
#include <cuda_bf16.h>
#include <cuda_fp16.h>
#include <cstdint>

#define NN 100000
#define EE 640000
#define DD 128
#define RR 64
#define LL 2

// ---- scratch (device globals; no allocations allowed) ----
__device__ float g_xw [NN * DD];
__device__ float g_x1 [NN * DD];
__device__ float g_gamma[LL * RR * DD];
__device__ float g_beta [LL * RR * DD];

// transposed film weights [l][k][j]
__device__ float g_fw0t[LL * 128 * 256];
__device__ float g_fw1t[LL * 256 * 256];
__device__ float g_fw2t[LL * 256 * 256];
__device__ float g_fw3t[LL * 256 * 256];

// CSR by destination
__device__ int      g_cnt[NN + 1];
__device__ int      g_off[NN + 1];
__device__ int      g_cur[NN];
__device__ uint32_t g_csr[EE];
__device__ int      g_bsum[64];

// bf16 hi/lo (gemm1 path)
__device__ __nv_bfloat16 g_xs_hi[NN * DD], g_xs_lo[NN * DD];   // x
__device__ __nv_bfloat16 g_w_hi[32768],    g_w_lo[32768];      // W_w both layers
// fp16 (gemm2/gemm3 path)
__device__ __half g_osf_hi[NN * DD],     g_osf_lo[NN * DD];      // out
__device__ __half g_hsf_hi[NN * 2 * DD], g_hsf_lo[NN * 2 * DD];  // h
__device__ __half g_w0f[65536], g_w1f[65536];                    // mlp weights fp16

// ============================ PTX helpers ============================
__device__ __forceinline__ uint32_t smem_u32(const void* p) {
    uint32_t a;
    asm("{ .reg .u64 t; cvta.to.shared.u64 t, %1; cvt.u32.u64 %0, t; }"
        : "=r"(a) : "l"(p));
    return a;
}
__device__ __forceinline__ void ldsm4(uint32_t* r, uint32_t addr) {
    asm volatile("ldmatrix.sync.aligned.m8n8.x4.shared.b16 {%0,%1,%2,%3}, [%4];"
                 : "=r"(r[0]), "=r"(r[1]), "=r"(r[2]), "=r"(r[3]) : "r"(addr));
}
__device__ __forceinline__ void mma_bf16(float* c, const uint32_t* a, const uint32_t* b) {
    asm volatile(
        "mma.sync.aligned.m16n8k16.row.col.f32.bf16.bf16.f32 "
        "{%0,%1,%2,%3}, {%4,%5,%6,%7}, {%8,%9}, {%0,%1,%2,%3};"
        : "+f"(c[0]), "+f"(c[1]), "+f"(c[2]), "+f"(c[3])
        : "r"(a[0]), "r"(a[1]), "r"(a[2]), "r"(a[3]), "r"(b[0]), "r"(b[1]));
}
__device__ __forceinline__ void mma_f16(float* c, const uint32_t* a, const uint32_t* b) {
    asm volatile(
        "mma.sync.aligned.m16n8k16.row.col.f32.f16.f16.f32 "
        "{%0,%1,%2,%3}, {%4,%5,%6,%7}, {%8,%9}, {%0,%1,%2,%3};"
        : "+f"(c[0]), "+f"(c[1]), "+f"(c[2]), "+f"(c[3])
        : "r"(a[0]), "r"(a[1]), "r"(a[2]), "r"(a[3]), "r"(b[0]), "r"(b[1]));
}
__device__ __forceinline__ void cpa16(uint32_t dst, const void* src, int sz) {
    asm volatile("cp.async.cg.shared.global [%0], [%1], 16, %2;"
                 :: "r"(dst), "l"(src), "r"(sz));
}
__device__ __forceinline__ void cpa_commit() {
    asm volatile("cp.async.commit_group;" ::: "memory");
}
__device__ __forceinline__ void cpa_wait0() {
    asm volatile("cp.async.wait_group 0;" ::: "memory");
}
__device__ __forceinline__ void cpa_wait1() {
    asm volatile("cp.async.wait_group 1;" ::: "memory");
}
__device__ __forceinline__ void cpa_wait2() {
    asm volatile("cp.async.wait_group 2;" ::: "memory");
}

__device__ __forceinline__ uint32_t pack_bf2(float a, float b) {
    __nv_bfloat16 h0 = __float2bfloat16(a), h1 = __float2bfloat16(b);
    return ((uint32_t)__bfloat16_as_ushort(h1) << 16) | __bfloat16_as_ushort(h0);
}
__device__ __forceinline__ uint32_t pack_h2(float a, float b) {
    __half h0 = __float2half_rn(a), h1 = __float2half_rn(b);
    return ((uint32_t)__half_as_ushort(h1) << 16) | __half_as_ushort(h0);
}

__device__ __forceinline__ void splitpack(const float* x, uint4& hi, uint4& lo) {
    uint32_t h[4], l[4];
    #pragma unroll
    for (int i = 0; i < 4; i++) {
        float x0 = x[2 * i], x1 = x[2 * i + 1];
        __nv_bfloat16 h0 = __float2bfloat16(x0);
        __nv_bfloat16 h1 = __float2bfloat16(x1);
        h[i] = ((uint32_t)__bfloat16_as_ushort(h1) << 16) | __bfloat16_as_ushort(h0);
        l[i] = pack_bf2(x0 - __bfloat162float(h0), x1 - __bfloat162float(h1));
    }
    hi = make_uint4(h[0], h[1], h[2], h[3]);
    lo = make_uint4(l[0], l[1], l[2], l[3]);
}

__global__ __launch_bounds__(256) void split8_kernel(
    const float* __restrict__ src, __nv_bfloat16* __restrict__ hi,
    __nv_bfloat16* __restrict__ lo, int n8)
{
    int i = blockIdx.x * blockDim.x + threadIdx.x;
    if (i >= n8) return;
    const float* p = src + (size_t)i * 8;
    float4 v0 = *(const float4*)p;
    float4 v1 = *(const float4*)(p + 4);
    float x[8] = {v0.x, v0.y, v0.z, v0.w, v1.x, v1.y, v1.z, v1.w};
    uint4 h, l;
    splitpack(x, h, l);
    *(uint4*)(hi + (size_t)i * 8) = h;
    *(uint4*)(lo + (size_t)i * 8) = l;
}

__global__ __launch_bounds__(256) void wconv_kernel(
    const float* __restrict__ w0, const float* __restrict__ w1,
    __half* __restrict__ o0, __half* __restrict__ o1, int n8each)
{
    int i = blockIdx.x * blockDim.x + threadIdx.x;
    if (i >= 2 * n8each) return;
    const float* src; __half* dst; int j;
    if (i < n8each) { src = w0; dst = o0; j = i; }
    else            { src = w1; dst = o1; j = i - n8each; }
    const float* p = src + (size_t)j * 8;
    float4 v0 = *(const float4*)p;
    float4 v1 = *(const float4*)(p + 4);
    uint4 o;
    o.x = pack_h2(v0.x, v0.y);
    o.y = pack_h2(v0.z, v0.w);
    o.z = pack_h2(v1.x, v1.y);
    o.w = pack_h2(v1.z, v1.w);
    *(uint4*)(dst + (size_t)j * 8) = o;
}

// transpose film weights -> [l][k][j]
__global__ __launch_bounds__(256) void filmt_kernel(
    const float* __restrict__ w0, const float* __restrict__ w1,
    const float* __restrict__ w2, const float* __restrict__ w3)
{
    int i = blockIdx.x * blockDim.x + threadIdx.x;
    const int S0 = LL * 128 * 256;      // w0t size
    const int S1 = LL * 256 * 256;
    if (i < S0) {
        int l = i / (128 * 256), rem = i % (128 * 256);
        int k = rem / 256, j = rem % 256;
        g_fw0t[i] = w0[(size_t)l * 256 * 128 + (size_t)j * 128 + k];
        return;
    }
    i -= S0;
    if (i < 3 * S1) {
        int which = i / S1, ii = i % S1;
        int l = ii / (256 * 256), rem = ii % (256 * 256);
        int k = rem / 256, j = rem % 256;
        const float* w = (which == 0) ? w1 : (which == 1) ? w2 : w3;
        float v = w[(size_t)l * 256 * 256 + (size_t)j * 256 + k];
        if (which == 0) g_fw1t[ii] = v;
        else if (which == 1) g_fw2t[ii] = v;
        else g_fw3t[ii] = v;
    }
}

// ============================ CSR build ============================
__global__ __launch_bounds__(256) void hist_kernel(const int* __restrict__ ei, int E) {
    int i = blockIdx.x * blockDim.x + threadIdx.x;
    if (i < E) atomicAdd(&g_cnt[ei[E + i]], 1);
}

#define SCAN_T 512
#define SCAN_E (SCAN_T * 4)
__global__ __launch_bounds__(SCAN_T) void scan1_kernel(int n) {
    __shared__ int sh[SCAN_T];
    int b = blockIdx.x, t = threadIdx.x;
    int base = b * SCAN_E + t * 4;
    int c[4], tot = 0;
    #pragma unroll
    for (int i = 0; i < 4; i++) {
        c[i] = (base + i < n) ? g_cnt[base + i] : 0;
        tot += c[i];
    }
    sh[t] = tot;
    __syncthreads();
    for (int d = 1; d < SCAN_T; d <<= 1) {
        int v = (t >= d) ? sh[t - d] : 0;
        __syncthreads();
        sh[t] += v;
        __syncthreads();
    }
    int run = sh[t] - tot;
    #pragma unroll
    for (int i = 0; i < 4; i++) {
        if (base + i < n) g_off[base + i] = run;
        run += c[i];
    }
    if (t == SCAN_T - 1) g_bsum[b] = sh[t];
}
__global__ __launch_bounds__(256) void scan23_kernel(int n, int E) {
    __shared__ int base;
    int b = blockIdx.x;
    if (threadIdx.x == 0) {
        int sbid = (b * 256) / SCAN_E;
        int s = 0;
        for (int i = 0; i < sbid; i++) s += g_bsum[i];
        base = s;
    }
    __syncthreads();
    int i = b * 256 + threadIdx.x;
    if (i < n) g_off[i] += base;
    if (i == 0) g_off[n] = E;
}
__global__ __launch_bounds__(256) void scatter_kernel(
    const int* __restrict__ ei, const int* __restrict__ et, int E)
{
    int i = blockIdx.x * blockDim.x + threadIdx.x;
    if (i >= E) return;
    int d = ei[E + i];
    int p = atomicAdd(&g_cur[d], 1);
    g_csr[g_off[d] + p] = (uint32_t)ei[i] | ((uint32_t)et[i] << 20);
}

// ============================ gather-aggregate ============================
// gamma/beta staged in dynamic smem (64KB); warp-per-node over grid stride.
#define GATHER_BLOCKS 444
__global__ __launch_bounds__(256) void gather_kernel(
    const float* __restrict__ xfp, const float* __restrict__ eps_ptr,
    int layer, int Mn)
{
    extern __shared__ float gsm[];       // [8192 gamma | 8192 beta]
    float* sg = gsm;
    float* sbta = gsm + 8192;
    const float* gam = g_gamma + (size_t)layer * RR * DD;
    const float* bet = g_beta  + (size_t)layer * RR * DD;

    for (int i = threadIdx.x; i < 2048; i += 256) {
        ((float4*)sg)[i]   = ((const float4*)gam)[i];
        ((float4*)sbta)[i] = ((const float4*)bet)[i];
    }
    __syncthreads();

    const int warp = threadIdx.x >> 5;
    const int lane = threadIdx.x & 31;
    const int c = lane * 4;
    const float scale = 1.f + eps_ptr[layer];

    for (int node = blockIdx.x * 8 + warp; node < Mn; node += gridDim.x * 8) {
        int beg = g_off[node];
        int end = g_off[node + 1];

        float4 acc = make_float4(0.f, 0.f, 0.f, 0.f);
        int e = beg;
        for (; e + 1 < end; e += 2) {
            uint32_t p0 = __ldg(&g_csr[e]);
            uint32_t p1 = __ldg(&g_csr[e + 1]);
            int s0 = p0 & 0xFFFFF, t0 = p0 >> 20;
            int s1 = p1 & 0xFFFFF, t1 = p1 >> 20;
            float4 x0 = *(const float4*)&g_xw[(size_t)s0 * 128 + c];
            float4 x1 = *(const float4*)&g_xw[(size_t)s1 * 128 + c];
            float4 gA = *(const float4*)&sg  [t0 * 128 + c];
            float4 bA = *(const float4*)&sbta[t0 * 128 + c];
            float4 gB = *(const float4*)&sg  [t1 * 128 + c];
            float4 bB = *(const float4*)&sbta[t1 * 128 + c];
            acc.x += fmaf(gA.x, x0.x, bA.x) + fmaf(gB.x, x1.x, bB.x);
            acc.y += fmaf(gA.y, x0.y, bA.y) + fmaf(gB.y, x1.y, bB.y);
            acc.z += fmaf(gA.z, x0.z, bA.z) + fmaf(gB.z, x1.z, bB.z);
            acc.w += fmaf(gA.w, x0.w, bA.w) + fmaf(gB.w, x1.w, bB.w);
        }
        if (e < end) {
            uint32_t p0 = __ldg(&g_csr[e]);
            int s0 = p0 & 0xFFFFF, t0 = p0 >> 20;
            float4 x0 = *(const float4*)&g_xw[(size_t)s0 * 128 + c];
            float4 gA = *(const float4*)&sg  [t0 * 128 + c];
            float4 bA = *(const float4*)&sbta[t0 * 128 + c];
            acc.x += fmaf(gA.x, x0.x, bA.x);
            acc.y += fmaf(gA.y, x0.y, bA.y);
            acc.z += fmaf(gA.z, x0.z, bA.z);
            acc.w += fmaf(gA.w, x0.w, bA.w);
        }

        float4 xv = *(const float4*)&xfp[(size_t)node * 128 + c];
        float o[4];
        o[0] = fmaf(scale, xv.x, acc.x);
        o[1] = fmaf(scale, xv.y, acc.y);
        o[2] = fmaf(scale, xv.z, acc.z);
        o[3] = fmaf(scale, xv.w, acc.w);

        __half h0 = __float2half_rn(o[0]);
        __half h1 = __float2half_rn(o[1]);
        __half h2 = __float2half_rn(o[2]);
        __half h3 = __float2half_rn(o[3]);
        uint2 hp, lp;
        hp.x = ((uint32_t)__half_as_ushort(h1) << 16) | __half_as_ushort(h0);
        hp.y = ((uint32_t)__half_as_ushort(h3) << 16) | __half_as_ushort(h2);
        lp.x = pack_h2(o[0] - __half2float(h0), o[1] - __half2float(h1));
        lp.y = pack_h2(o[2] - __half2float(h2), o[3] - __half2float(h3));
        *(uint2*)&g_osf_hi[(size_t)node * 128 + c] = hp;
        *(uint2*)&g_osf_lo[(size_t)node * 128 + c] = lp;
    }
}

// ---------------------------------------------------------------------------
// FiLM kernel v4: cp.async 4-stage weight tile stream over transposed weights.
// grid = RR * LL; 256 threads. 56 tiles of 16k x 256j (16KB each).
// ---------------------------------------------------------------------------
#define FILM_SMEM 65536
__global__ __launch_bounds__(256) void film_kernel(
    const float* __restrict__ rel,
    const float* __restrict__ b0, const float* __restrict__ b1,
    const float* __restrict__ b2, const float* __restrict__ b3)
{
    extern __shared__ float fsm[];               // 4 stages x 4096 floats
    __shared__ float bufA[256];
    __shared__ float bufB[256];
    const uint32_t fb = smem_u32(fsm);

    const int bid = blockIdx.x;
    const int r = bid & (RR - 1);
    const int l = bid >> 6;
    const int tid = threadIdx.x;

    const float* wt_src[4] = {
        g_fw0t + (size_t)l * 128 * 256,
        g_fw1t + (size_t)l * 256 * 256,
        g_fw2t + (size_t)l * 256 * 256,
        g_fw3t + (size_t)l * 256 * 256
    };
    const int tcnt[4] = {8, 16, 16, 16};
    const float* bias_src[4] = {
        b0 + (size_t)l * 256, b1 + (size_t)l * 256,
        b2 + (size_t)l * 256, b3 + (size_t)l * 256
    };
    const int NT = 56;

    if (tid < 128) bufA[tid] = rel[((size_t)l * RR + r) * 128 + tid];

    auto issue = [&](int t) {
        if (t < NT) {
            int tt = t, l4 = 0;
            while (tt >= tcnt[l4]) { tt -= tcnt[l4]; l4++; }
            const float* src = wt_src[l4] + (size_t)tt * 16 * 256 + tid * 16;
            uint32_t dst = fb + (uint32_t)(t & 3) * 16384 + tid * 64;
            #pragma unroll
            for (int q = 0; q < 4; q++) cpa16(dst + q * 16, src + q * 4, 16);
        }
        cpa_commit();
    };

    issue(0); issue(1); issue(2);

    float acc = bias_src[0][tid];
    float* srcbuf = bufA;
    float* dstbuf = bufB;
    int l4 = 0, tin = 0;
    __syncthreads();   // bufA visible

    for (int t = 0; t < NT; t++) {
        cpa_wait2();
        __syncthreads();
        const float* stg = fsm + (t & 3) * 4096;
        const int kb = tin * 16;
        #pragma unroll
        for (int k = 0; k < 16; k++)
            acc = fmaf(stg[k * 256 + tid], srcbuf[kb + k], acc);
        tin++;
        if (tin == tcnt[l4]) {
            if (l4 < 3) {
                dstbuf[tid] = fmaxf(acc, 0.f);
            } else {
                size_t o = ((size_t)l * RR + r) * 128;
                if (tid < 128) g_gamma[o + tid] = acc;
                else           g_beta [o + (tid - 128)] = acc;
            }
            __syncthreads();
            float* tmp = srcbuf; srcbuf = dstbuf; dstbuf = tmp;
            tin = 0; l4++;
            if (l4 < 4) acc = bias_src[l4][tid];
        } else {
            __syncthreads();
        }
        issue(t + 3);
    }
}

// ---------------------------------------------------------------------------
// Common tiling constants
// ---------------------------------------------------------------------------
#define BK 32
#define PITCH 40
#define TILE_B (128 * PITCH * 2)        // 10240 B
#define STAGE_BF (4 * TILE_B)
#define GSMEM_BF (2 * STAGE_BF)         // 81920
#define STAGE_FP (3 * TILE_B)
#define GSMEM_FP (2 * STAGE_FP)         // 61440

// ---------------------------------------------------------------------------
// gemm_bf: 3-term bf16 (gemm1 only). C = A@B^T + bias, fp32 out.
// ---------------------------------------------------------------------------
__global__ __launch_bounds__(256) void gemm_bf(
    const __nv_bfloat16* __restrict__ Ah, const __nv_bfloat16* __restrict__ Al,
    const __nv_bfloat16* __restrict__ Bh, const __nv_bfloat16* __restrict__ Bl,
    const float* __restrict__ bias, float* __restrict__ C,
    int M, int N, int K)
{
    extern __shared__ char smem[];
    const uint32_t sb = smem_u32(smem);

    const int tid  = threadIdx.x;
    const int wid  = tid >> 5;
    const int lane = tid & 31;
    const int bm0  = blockIdx.x * 128;
    const int bn0  = blockIdx.y * 128;
    const int wm   = (wid & 3) * 32;
    const int wn   = (wid >> 2) * 64;

    float acc[2][8][4];
    #pragma unroll
    for (int mt = 0; mt < 2; mt++)
        #pragma unroll
        for (int nt = 0; nt < 8; nt++)
            #pragma unroll
            for (int q = 0; q < 4; q++) acc[mt][nt][q] = 0.f;

    const __nv_bfloat16* gA[2] = {Ah, Al};
    const __nv_bfloat16* gB[2] = {Bh, Bl};

    auto prefetch = [&](int stage, int ch) {
        const int k0 = ch * BK;
        const uint32_t base = sb + stage * STAGE_BF;
        #pragma unroll
        for (int hl = 0; hl < 2; hl++)
            #pragma unroll
            for (int it = 0; it < 2; it++) {
                int c = tid + it * 256;
                int row = c >> 2;
                int col8 = (c & 3) << 3;
                uint32_t dst = base + hl * TILE_B + (uint32_t)(row * PITCH + col8) * 2;
                int gr = bm0 + row;
                int ok = (gr < M) ? 16 : 0;
                cpa16(dst, gA[hl] + (size_t)(ok ? gr : 0) * K + k0 + col8, ok);
            }
        #pragma unroll
        for (int hl = 0; hl < 2; hl++)
            #pragma unroll
            for (int it = 0; it < 2; it++) {
                int c = tid + it * 256;
                int row = c >> 2;
                int col8 = (c & 3) << 3;
                uint32_t dst = base + (2 + hl) * TILE_B + (uint32_t)(row * PITCH + col8) * 2;
                cpa16(dst, gB[hl] + (size_t)(bn0 + row) * K + k0 + col8, 16);
            }
        cpa_commit();
    };

    const int a_row = lane & 15;
    const int a_cb  = (lane >> 4) << 3;
    const int b_g   = lane >> 3;
    const int b_r   = lane & 7;
    const int b_row = ((b_g >> 1) << 3) + b_r;
    const int b_cb  = (b_g & 1) << 3;

    const int nchunk = K >> 5;
    prefetch(0, 0);

    for (int ch = 0; ch < nchunk; ch++) {
        const int stage = ch & 1;
        if (ch + 1 < nchunk) { prefetch(stage ^ 1, ch + 1); cpa_wait1(); }
        else                 { cpa_wait0(); }
        __syncthreads();

        const uint32_t base = sb + stage * STAGE_BF;
        #pragma unroll
        for (int ks = 0; ks < 2; ks++) {
            const int kk = ks << 4;
            uint32_t ah[2][4], al[2][4], bh[8][2], bl[8][2];
            #pragma unroll
            for (int mt = 0; mt < 2; mt++) {
                uint32_t off = (uint32_t)((wm + mt * 16 + a_row) * PITCH + kk + a_cb) * 2;
                ldsm4(ah[mt], base + off);
                ldsm4(al[mt], base + TILE_B + off);
            }
            #pragma unroll
            for (int nb = 0; nb < 4; nb++) {
                uint32_t off = (uint32_t)((wn + nb * 16 + b_row) * PITCH + kk + b_cb) * 2;
                uint32_t r[4];
                ldsm4(r, base + 2 * TILE_B + off);
                bh[nb*2][0]=r[0]; bh[nb*2][1]=r[1]; bh[nb*2+1][0]=r[2]; bh[nb*2+1][1]=r[3];
                ldsm4(r, base + 3 * TILE_B + off);
                bl[nb*2][0]=r[0]; bl[nb*2][1]=r[1]; bl[nb*2+1][0]=r[2]; bl[nb*2+1][1]=r[3];
            }
            #pragma unroll
            for (int mt = 0; mt < 2; mt++)
                #pragma unroll
                for (int nt = 0; nt < 8; nt++) {
                    mma_bf16(acc[mt][nt], ah[mt], bh[nt]);
                    mma_bf16(acc[mt][nt], ah[mt], bl[nt]);
                    mma_bf16(acc[mt][nt], al[mt], bh[nt]);
                }
        }
        __syncthreads();
    }

    const int gid = lane >> 2;
    const int tig = lane & 3;
    #pragma unroll
    for (int nt = 0; nt < 8; nt++) {
        int col = bn0 + wn + nt * 8 + tig * 2;
        float2 bv = *(const float2*)&bias[col];
        #pragma unroll
        for (int mt = 0; mt < 2; mt++) {
            int r0 = bm0 + wm + mt * 16 + gid;
            int r1 = r0 + 8;
            float2 o0, o1;
            o0.x = acc[mt][nt][0] + bv.x; o0.y = acc[mt][nt][1] + bv.y;
            o1.x = acc[mt][nt][2] + bv.x; o1.y = acc[mt][nt][3] + bv.y;
            if (r0 < M) *(float2*)(C + (size_t)r0 * N + col) = o0;
            if (r1 < M) *(float2*)(C + (size_t)r1 * N + col) = o1;
        }
    }
}

// ---------------------------------------------------------------------------
// gemm_fp: 2-term fp16 (A hi/lo fp16, B single fp16).
// OSPLIT: 0 none, 1 fp16 hi/lo, 2 bf16 hi/lo.  FP32_OUT: write fp32 C.
// ---------------------------------------------------------------------------
template <bool RELU, int OSPLIT, bool FP32_OUT>
__global__ __launch_bounds__(256) void gemm_fp(
    const __half* __restrict__ Ah, const __half* __restrict__ Al,
    const __half* __restrict__ B,
    const float* __restrict__ bias, float* __restrict__ C,
    void* __restrict__ Ch, void* __restrict__ Cl,
    int M, int N, int K)
{
    extern __shared__ char smem[];
    const uint32_t sb = smem_u32(smem);

    const int tid  = threadIdx.x;
    const int wid  = tid >> 5;
    const int lane = tid & 31;
    const int bm0  = blockIdx.x * 128;
    const int bn0  = blockIdx.y * 128;
    const int wm   = (wid & 3) * 32;
    const int wn   = (wid >> 2) * 64;

    float acc[2][8][4];
    #pragma unroll
    for (int mt = 0; mt < 2; mt++)
        #pragma unroll
        for (int nt = 0; nt < 8; nt++)
            #pragma unroll
            for (int q = 0; q < 4; q++) acc[mt][nt][q] = 0.f;

    const __half* gA[2] = {Ah, Al};

    auto prefetch = [&](int stage, int ch) {
        const int k0 = ch * BK;
        const uint32_t base = sb + stage * STAGE_FP;
        #pragma unroll
        for (int hl = 0; hl < 2; hl++)
            #pragma unroll
            for (int it = 0; it < 2; it++) {
                int c = tid + it * 256;
                int row = c >> 2;
                int col8 = (c & 3) << 3;
                uint32_t dst = base + hl * TILE_B + (uint32_t)(row * PITCH + col8) * 2;
                int gr = bm0 + row;
                int ok = (gr < M) ? 16 : 0;
                cpa16(dst, gA[hl] + (size_t)(ok ? gr : 0) * K + k0 + col8, ok);
            }
        #pragma unroll
        for (int it = 0; it < 2; it++) {
            int c = tid + it * 256;
            int row = c >> 2;
            int col8 = (c & 3) << 3;
            uint32_t dst = base + 2 * TILE_B + (uint32_t)(row * PITCH + col8) * 2;
            cpa16(dst, B + (size_t)(bn0 + row) * K + k0 + col8, 16);
        }
        cpa_commit();
    };

    const int a_row = lane & 15;
    const int a_cb  = (lane >> 4) << 3;
    const int b_g   = lane >> 3;
    const int b_r   = lane & 7;
    const int b_row = ((b_g >> 1) << 3) + b_r;
    const int b_cb  = (b_g & 1) << 3;

    const int nchunk = K >> 5;
    prefetch(0, 0);

    for (int ch = 0; ch < nchunk; ch++) {
        const int stage = ch & 1;
        if (ch + 1 < nchunk) { prefetch(stage ^ 1, ch + 1); cpa_wait1(); }
        else                 { cpa_wait0(); }
        __syncthreads();

        const uint32_t base = sb + stage * STAGE_FP;
        #pragma unroll
        for (int ks = 0; ks < 2; ks++) {
            const int kk = ks << 4;
            uint32_t ah[2][4], al[2][4], bh[8][2];
            #pragma unroll
            for (int mt = 0; mt < 2; mt++) {
                uint32_t off = (uint32_t)((wm + mt * 16 + a_row) * PITCH + kk + a_cb) * 2;
                ldsm4(ah[mt], base + off);
                ldsm4(al[mt], base + TILE_B + off);
            }
            #pragma unroll
            for (int nb = 0; nb < 4; nb++) {
                uint32_t off = (uint32_t)((wn + nb * 16 + b_row) * PITCH + kk + b_cb) * 2;
                uint32_t r[4];
                ldsm4(r, base + 2 * TILE_B + off);
                bh[nb*2][0]=r[0]; bh[nb*2][1]=r[1]; bh[nb*2+1][0]=r[2]; bh[nb*2+1][1]=r[3];
            }
            #pragma unroll
            for (int mt = 0; mt < 2; mt++)
                #pragma unroll
                for (int nt = 0; nt < 8; nt++) {
                    mma_f16(acc[mt][nt], ah[mt], bh[nt]);
                    mma_f16(acc[mt][nt], al[mt], bh[nt]);
                }
        }
        __syncthreads();
    }

    const int gid = lane >> 2;
    const int tig = lane & 3;
    #pragma unroll
    for (int nt = 0; nt < 8; nt++) {
        int col = bn0 + wn + nt * 8 + tig * 2;
        float2 bv = *(const float2*)&bias[col];
        #pragma unroll
        for (int mt = 0; mt < 2; mt++) {
            int rr[2] = {bm0 + wm + mt * 16 + gid, bm0 + wm + mt * 16 + gid + 8};
            float2 oo[2];
            oo[0].x = acc[mt][nt][0] + bv.x; oo[0].y = acc[mt][nt][1] + bv.y;
            oo[1].x = acc[mt][nt][2] + bv.x; oo[1].y = acc[mt][nt][3] + bv.y;
            #pragma unroll
            for (int u = 0; u < 2; u++) {
                if (rr[u] >= M) continue;
                float2 o = oo[u];
                if (RELU) { o.x = fmaxf(o.x, 0.f); o.y = fmaxf(o.y, 0.f); }
                if (FP32_OUT) *(float2*)(C + (size_t)rr[u] * N + col) = o;
                if (OSPLIT == 1) {
                    __half h0 = __float2half_rn(o.x);
                    __half h1 = __float2half_rn(o.y);
                    uint32_t hp = ((uint32_t)__half_as_ushort(h1) << 16) | __half_as_ushort(h0);
                    uint32_t lp = pack_h2(o.x - __half2float(h0), o.y - __half2float(h1));
                    *(uint32_t*)((__half*)Ch + (size_t)rr[u] * N + col) = hp;
                    *(uint32_t*)((__half*)Cl + (size_t)rr[u] * N + col) = lp;
                } else if (OSPLIT == 2) {
                    __nv_bfloat16 h0 = __float2bfloat16(o.x);
                    __nv_bfloat16 h1 = __float2bfloat16(o.y);
                    uint32_t hp = ((uint32_t)__bfloat16_as_ushort(h1) << 16) | __bfloat16_as_ushort(h0);
                    uint32_t lp = pack_bf2(o.x - __bfloat162float(h0), o.y - __bfloat162float(h1));
                    *(uint32_t*)((__nv_bfloat16*)Ch + (size_t)rr[u] * N + col) = hp;
                    *(uint32_t*)((__nv_bfloat16*)Cl + (size_t)rr[u] * N + col) = lp;
                }
            }
        }
    }
}

// ---------------------------------------------------------------------------
extern "C" void kernel_launch(void* const* d_in, const int* in_sizes, int n_in,
                              void* d_out, int out_size)
{
    const int* edge_index = (const int*)d_in[0];
    const int* edge_type  = (const int*)d_in[1];
    const float* embed_w = (const float*)d_in[2];
    const float* rel_emb = (const float*)d_in[3];
    const float* rmw0 = (const float*)d_in[4];
    const float* rmb0 = (const float*)d_in[5];
    const float* rmw1 = (const float*)d_in[6];
    const float* rmb1 = (const float*)d_in[7];
    const float* rmw2 = (const float*)d_in[8];
    const float* rmb2 = (const float*)d_in[9];
    const float* rmw3 = (const float*)d_in[10];
    const float* rmb3 = (const float*)d_in[11];
    const float* W_w  = (const float*)d_in[12];
    const float* W_b  = (const float*)d_in[13];
    const float* mlp_w0 = (const float*)d_in[14];
    const float* mlp_b0 = (const float*)d_in[15];
    const float* mlp_w1 = (const float*)d_in[16];
    const float* mlp_b1 = (const float*)d_in[17];
    const float* eps    = (const float*)d_in[18];

    const int E = in_sizes[1];
    const int M = in_sizes[2] / DD;

    cudaFuncSetAttribute(gemm_bf,
                         cudaFuncAttributeMaxDynamicSharedMemorySize, GSMEM_BF);
    cudaFuncSetAttribute(gemm_fp<true,  1, false>,
                         cudaFuncAttributeMaxDynamicSharedMemorySize, GSMEM_FP);
    cudaFuncSetAttribute(gemm_fp<false, 2, true>,
                         cudaFuncAttributeMaxDynamicSharedMemorySize, GSMEM_FP);
    cudaFuncSetAttribute(gemm_fp<false, 0, true>,
                         cudaFuncAttributeMaxDynamicSharedMemorySize, GSMEM_FP);
    cudaFuncSetAttribute(film_kernel,
                         cudaFuncAttributeMaxDynamicSharedMemorySize, FILM_SMEM);
    cudaFuncSetAttribute(gather_kernel,
                         cudaFuncAttributeMaxDynamicSharedMemorySize, 65536);

    float *xw, *x1;
    int *cnt, *cur;
    __nv_bfloat16 *xs_h, *xs_l, *w_h, *w_l;
    __half *os_h, *os_l, *hs_h, *hs_l, *w0f, *w1f;
    cudaGetSymbolAddress((void**)&xw,   g_xw);
    cudaGetSymbolAddress((void**)&x1,   g_x1);
    cudaGetSymbolAddress((void**)&cnt,  g_cnt);
    cudaGetSymbolAddress((void**)&cur,  g_cur);
    cudaGetSymbolAddress((void**)&xs_h, g_xs_hi);
    cudaGetSymbolAddress((void**)&xs_l, g_xs_lo);
    cudaGetSymbolAddress((void**)&w_h,  g_w_hi);
    cudaGetSymbolAddress((void**)&w_l,  g_w_lo);
    cudaGetSymbolAddress((void**)&os_h, g_osf_hi);
    cudaGetSymbolAddress((void**)&os_l, g_osf_lo);
    cudaGetSymbolAddress((void**)&hs_h, g_hsf_hi);
    cudaGetSymbolAddress((void**)&hs_l, g_hsf_lo);
    cudaGetSymbolAddress((void**)&w0f,  g_w0f);
    cudaGetSymbolAddress((void**)&w1f,  g_w1f);

    const int GB = (M + 127) / 128;

    // prep
    {
        int n8 = M * DD / 8;
        split8_kernel<<<(n8 + 255)/256, 256>>>(embed_w, xs_h, xs_l, n8);
    }
    split8_kernel<<<(32768/8 + 255)/256, 256>>>(W_w, w_h, w_l, 32768/8);
    wconv_kernel<<<(2*8192 + 255)/256, 256>>>(mlp_w0, mlp_w1, w0f, w1f, 8192);
    {
        int tot = LL * 128 * 256 + 3 * LL * 256 * 256;
        filmt_kernel<<<(tot + 255)/256, 256>>>(rmw0, rmw1, rmw2, rmw3);
    }
    film_kernel<<<RR * LL, 256, FILM_SMEM>>>(rel_emb, rmb0, rmb1, rmb2, rmb3);
    cudaMemsetAsync(cnt, 0, (size_t)(M + 1) * sizeof(int));
    cudaMemsetAsync(cur, 0, (size_t)M * sizeof(int));
    hist_kernel<<<(E + 255) / 256, 256>>>(edge_index, E);
    gemm_bf<<<dim3(GB, 1), 256, GSMEM_BF>>>(
        xs_h, xs_l, w_h, w_l, W_b, xw, M, 128, 128);
    int nsb = (M + SCAN_E - 1) / SCAN_E;
    scan1_kernel<<<nsb, SCAN_T>>>(M);
    scan23_kernel<<<(M + 255) / 256, 256>>>(M, E);
    scatter_kernel<<<(E + 255) / 256, 256>>>(edge_index, edge_type, E);

    for (int l = 0; l < LL; l++) {
        const float* x_fp32 = (l == 0) ? embed_w : x1;

        if (l > 0) {
            gemm_bf<<<dim3(GB, 1), 256, GSMEM_BF>>>(
                xs_h, xs_l, w_h + l * 16384, w_l + l * 16384,
                W_b + (size_t)l * 128, xw, M, 128, 128);
        }

        gather_kernel<<<GATHER_BLOCKS, 256, 65536>>>(x_fp32, eps, l, M);

        gemm_fp<true, 1, false><<<dim3(GB, 2), 256, GSMEM_FP>>>(
            os_h, os_l, w0f + (size_t)l * 32768,
            mlp_b0 + (size_t)l * 256, nullptr, hs_h, hs_l, M, 256, 128);

        if (l < LL - 1) {
            gemm_fp<false, 2, true><<<dim3(GB, 1), 256, GSMEM_FP>>>(
                hs_h, hs_l, w1f + (size_t)l * 32768,
                mlp_b1 + (size_t)l * 128, x1, xs_h, xs_l, M, 128, 256);
        } else {
            gemm_fp<false, 0, true><<<dim3(GB, 1), 256, GSMEM_FP>>>(
                hs_h, hs_l, w1f + (size_t)l * 32768,
                mlp_b1 + (size_t)l * 128, (float*)d_out, nullptr, nullptr, M, 128, 256);
        }
    }
}

// round 14
// speedup vs baseline: 1.0939x; 1.0939x over previous
#include <cuda_runtime.h>
#include <cuda_bf16.h>
#include <cuda_fp16.h>
#include <cstdint>

#define NN 100000
#define EE 640000
#define DD 128
#define RR 64
#define LL 2

// ---- scratch (device globals; no allocations allowed) ----
__device__ float g_xw [NN * DD];
__device__ float g_x1 [NN * DD];
__device__ float g_gamma[LL * RR * DD];
__device__ float g_beta [LL * RR * DD];

// CSR by destination
__device__ int      g_cnt[NN + 1];
__device__ int      g_off[NN + 1];
__device__ int      g_cur[NN];
__device__ uint32_t g_csr[EE];
__device__ int      g_bsum[64];

// fp16 activation / weight buffers
__device__ __half g_xs_hi[NN * DD],      g_xs_lo[NN * DD];       // x hi/lo
__device__ __half g_osf_hi[NN * DD],     g_osf_lo[NN * DD];      // out hi/lo
__device__ __half g_hsf_hi[NN * 2 * DD], g_hsf_lo[NN * 2 * DD];  // h hi/lo
__device__ __half g_wwf[32768];                                  // W_w fp16 (both layers)
__device__ __half g_w0f[65536], g_w1f[65536];                    // mlp weights fp16

// ============================ PTX helpers ============================
__device__ __forceinline__ uint32_t smem_u32(const void* p) {
    uint32_t a;
    asm("{ .reg .u64 t; cvta.to.shared.u64 t, %1; cvt.u32.u64 %0, t; }"
        : "=r"(a) : "l"(p));
    return a;
}
__device__ __forceinline__ void ldsm4(uint32_t* r, uint32_t addr) {
    asm volatile("ldmatrix.sync.aligned.m8n8.x4.shared.b16 {%0,%1,%2,%3}, [%4];"
                 : "=r"(r[0]), "=r"(r[1]), "=r"(r[2]), "=r"(r[3]) : "r"(addr));
}
__device__ __forceinline__ void mma_f16(float* c, const uint32_t* a, const uint32_t* b) {
    asm volatile(
        "mma.sync.aligned.m16n8k16.row.col.f32.f16.f16.f32 "
        "{%0,%1,%2,%3}, {%4,%5,%6,%7}, {%8,%9}, {%0,%1,%2,%3};"
        : "+f"(c[0]), "+f"(c[1]), "+f"(c[2]), "+f"(c[3])
        : "r"(a[0]), "r"(a[1]), "r"(a[2]), "r"(a[3]), "r"(b[0]), "r"(b[1]));
}
__device__ __forceinline__ void cpa16(uint32_t dst, const void* src, int sz) {
    asm volatile("cp.async.cg.shared.global [%0], [%1], 16, %2;"
                 :: "r"(dst), "l"(src), "r"(sz));
}
__device__ __forceinline__ void cpa_commit() {
    asm volatile("cp.async.commit_group;" ::: "memory");
}
__device__ __forceinline__ void cpa_wait0() {
    asm volatile("cp.async.wait_group 0;" ::: "memory");
}
__device__ __forceinline__ void cpa_wait1() {
    asm volatile("cp.async.wait_group 1;" ::: "memory");
}

__device__ __forceinline__ uint32_t pack_h2(float a, float b) {
    __half h0 = __float2half_rn(a), h1 = __float2half_rn(b);
    return ((uint32_t)__half_as_ushort(h1) << 16) | __half_as_ushort(h0);
}

// elementwise fp32 -> fp16 hi/lo split, 8 elems/thread
__global__ __launch_bounds__(256) void split8h_kernel(
    const float* __restrict__ src, __half* __restrict__ hi,
    __half* __restrict__ lo, int n8)
{
    int i = blockIdx.x * blockDim.x + threadIdx.x;
    if (i >= n8) return;
    const float* p = src + (size_t)i * 8;
    float4 v0 = *(const float4*)p;
    float4 v1 = *(const float4*)(p + 4);
    float x[8] = {v0.x, v0.y, v0.z, v0.w, v1.x, v1.y, v1.z, v1.w};
    uint32_t h[4], l[4];
    #pragma unroll
    for (int q = 0; q < 4; q++) {
        float x0 = x[2 * q], x1 = x[2 * q + 1];
        __half h0 = __float2half_rn(x0), h1 = __float2half_rn(x1);
        h[q] = ((uint32_t)__half_as_ushort(h1) << 16) | __half_as_ushort(h0);
        l[q] = pack_h2(x0 - __half2float(h0), x1 - __half2float(h1));
    }
    *(uint4*)(hi + (size_t)i * 8) = make_uint4(h[0], h[1], h[2], h[3]);
    *(uint4*)(lo + (size_t)i * 8) = make_uint4(l[0], l[1], l[2], l[3]);
}

// fp32 -> fp16 plain convert
__global__ __launch_bounds__(256) void hconv_kernel(
    const float* __restrict__ src, __half* __restrict__ dst, int n8)
{
    int i = blockIdx.x * blockDim.x + threadIdx.x;
    if (i >= n8) return;
    const float* p = src + (size_t)i * 8;
    float4 v0 = *(const float4*)p;
    float4 v1 = *(const float4*)(p + 4);
    uint4 o;
    o.x = pack_h2(v0.x, v0.y);
    o.y = pack_h2(v0.z, v0.w);
    o.z = pack_h2(v1.x, v1.y);
    o.w = pack_h2(v1.z, v1.w);
    *(uint4*)(dst + (size_t)i * 8) = o;
}

// convert mlp weights fp32 -> fp16 (both arrays in one launch)
__global__ __launch_bounds__(256) void wconv_kernel(
    const float* __restrict__ w0, const float* __restrict__ w1,
    __half* __restrict__ o0, __half* __restrict__ o1, int n8each)
{
    int i = blockIdx.x * blockDim.x + threadIdx.x;
    if (i >= 2 * n8each) return;
    const float* src; __half* dst; int j;
    if (i < n8each) { src = w0; dst = o0; j = i; }
    else            { src = w1; dst = o1; j = i - n8each; }
    const float* p = src + (size_t)j * 8;
    float4 v0 = *(const float4*)p;
    float4 v1 = *(const float4*)(p + 4);
    uint4 o;
    o.x = pack_h2(v0.x, v0.y);
    o.y = pack_h2(v0.z, v0.w);
    o.z = pack_h2(v1.x, v1.y);
    o.w = pack_h2(v1.z, v1.w);
    *(uint4*)(dst + (size_t)j * 8) = o;
}

// ============================ CSR build ============================
__global__ __launch_bounds__(256) void hist_kernel(const int* __restrict__ ei, int E) {
    int i = blockIdx.x * blockDim.x + threadIdx.x;
    if (i < E) atomicAdd(&g_cnt[ei[E + i]], 1);
}

#define SCAN_T 512
#define SCAN_E (SCAN_T * 4)
__global__ __launch_bounds__(SCAN_T) void scan1_kernel(int n) {
    __shared__ int sh[SCAN_T];
    int b = blockIdx.x, t = threadIdx.x;
    int base = b * SCAN_E + t * 4;
    int c[4], tot = 0;
    #pragma unroll
    for (int i = 0; i < 4; i++) {
        c[i] = (base + i < n) ? g_cnt[base + i] : 0;
        tot += c[i];
    }
    sh[t] = tot;
    __syncthreads();
    for (int d = 1; d < SCAN_T; d <<= 1) {
        int v = (t >= d) ? sh[t - d] : 0;
        __syncthreads();
        sh[t] += v;
        __syncthreads();
    }
    int run = sh[t] - tot;
    #pragma unroll
    for (int i = 0; i < 4; i++) {
        if (base + i < n) g_off[base + i] = run;
        run += c[i];
    }
    if (t == SCAN_T - 1) g_bsum[b] = sh[t];
}
__global__ __launch_bounds__(256) void scan23_kernel(int n, int E) {
    __shared__ int base;
    int b = blockIdx.x;
    if (threadIdx.x == 0) {
        int sbid = (b * 256) / SCAN_E;
        int s = 0;
        for (int i = 0; i < sbid; i++) s += g_bsum[i];
        base = s;
    }
    __syncthreads();
    int i = b * 256 + threadIdx.x;
    if (i < n) g_off[i] += base;
    if (i == 0) g_off[n] = E;
}
__global__ __launch_bounds__(256) void scatter_kernel(
    const int* __restrict__ ei, const int* __restrict__ et, int E)
{
    int i = blockIdx.x * blockDim.x + threadIdx.x;
    if (i >= E) return;
    int d = ei[E + i];
    int p = atomicAdd(&g_cur[d], 1);
    g_csr[g_off[d] + p] = (uint32_t)ei[i] | ((uint32_t)et[i] << 20);
}

// ============================ gather-aggregate ============================
__global__ __launch_bounds__(256) void gather_kernel(
    const float* __restrict__ xfp, const float* __restrict__ eps_ptr,
    int layer, int Mn)
{
    int node = (int)((blockIdx.x * blockDim.x + threadIdx.x) >> 5);
    if (node >= Mn) return;
    int lane = threadIdx.x & 31;
    int c = lane * 4;

    const float* gam = g_gamma + (size_t)layer * RR * DD;
    const float* bet = g_beta  + (size_t)layer * RR * DD;

    int beg = g_off[node];
    int end = g_off[node + 1];

    float4 acc = make_float4(0.f, 0.f, 0.f, 0.f);
    int e = beg;
    for (; e + 1 < end; e += 2) {
        uint32_t p0 = __ldg(&g_csr[e]);
        uint32_t p1 = __ldg(&g_csr[e + 1]);
        int s0 = p0 & 0xFFFFF, t0 = p0 >> 20;
        int s1 = p1 & 0xFFFFF, t1 = p1 >> 20;
        float4 x0 = *(const float4*)&g_xw[(size_t)s0 * 128 + c];
        float4 x1 = *(const float4*)&g_xw[(size_t)s1 * 128 + c];
        float4 gA = *(const float4*)&gam[(size_t)t0 * 128 + c];
        float4 bA = *(const float4*)&bet[(size_t)t0 * 128 + c];
        float4 gB = *(const float4*)&gam[(size_t)t1 * 128 + c];
        float4 bB = *(const float4*)&bet[(size_t)t1 * 128 + c];
        acc.x += fmaf(gA.x, x0.x, bA.x) + fmaf(gB.x, x1.x, bB.x);
        acc.y += fmaf(gA.y, x0.y, bA.y) + fmaf(gB.y, x1.y, bB.y);
        acc.z += fmaf(gA.z, x0.z, bA.z) + fmaf(gB.z, x1.z, bB.z);
        acc.w += fmaf(gA.w, x0.w, bA.w) + fmaf(gB.w, x1.w, bB.w);
    }
    if (e < end) {
        uint32_t p0 = __ldg(&g_csr[e]);
        int s0 = p0 & 0xFFFFF, t0 = p0 >> 20;
        float4 x0 = *(const float4*)&g_xw[(size_t)s0 * 128 + c];
        float4 gA = *(const float4*)&gam[(size_t)t0 * 128 + c];
        float4 bA = *(const float4*)&bet[(size_t)t0 * 128 + c];
        acc.x += fmaf(gA.x, x0.x, bA.x);
        acc.y += fmaf(gA.y, x0.y, bA.y);
        acc.z += fmaf(gA.z, x0.z, bA.z);
        acc.w += fmaf(gA.w, x0.w, bA.w);
    }

    float scale = 1.f + eps_ptr[layer];
    float4 xv = *(const float4*)&xfp[(size_t)node * 128 + c];
    float o[4];
    o[0] = fmaf(scale, xv.x, acc.x);
    o[1] = fmaf(scale, xv.y, acc.y);
    o[2] = fmaf(scale, xv.z, acc.z);
    o[3] = fmaf(scale, xv.w, acc.w);

    __half h0 = __float2half_rn(o[0]);
    __half h1 = __float2half_rn(o[1]);
    __half h2 = __float2half_rn(o[2]);
    __half h3 = __float2half_rn(o[3]);
    uint2 hp, lp;
    hp.x = ((uint32_t)__half_as_ushort(h1) << 16) | __half_as_ushort(h0);
    hp.y = ((uint32_t)__half_as_ushort(h3) << 16) | __half_as_ushort(h2);
    lp.x = pack_h2(o[0] - __half2float(h0), o[1] - __half2float(h1));
    lp.y = pack_h2(o[2] - __half2float(h2), o[3] - __half2float(h3));
    *(uint2*)&g_osf_hi[(size_t)node * 128 + c] = hp;
    *(uint2*)&g_osf_lo[(size_t)node * 128 + c] = lp;
}

// ---------------------------------------------------------------------------
// FiLM kernel v3 (R11, proven): register-prefetch pipelined weight tiles,
// BOTH layers in one launch. grid = RR * LL.
// ---------------------------------------------------------------------------
__global__ __launch_bounds__(256) void film_kernel(
    const float* __restrict__ rel,
    const float* __restrict__ w0, const float* __restrict__ b0,
    const float* __restrict__ w1, const float* __restrict__ b1,
    const float* __restrict__ w2, const float* __restrict__ b2,
    const float* __restrict__ w3, const float* __restrict__ b3)
{
    __shared__ float act[256];
    __shared__ float nxt[256];
    __shared__ float wt[16][257];

    const int bid = blockIdx.x;
    const int r = bid & (RR - 1);
    const int l = bid >> 6;
    const int tid = threadIdx.x;
    const int lk = tid & 15;
    const int lj = tid >> 4;

    const float* W0 = w0 + (size_t)l * 256 * 128;
    const float* B0 = b0 + (size_t)l * 256;
    const float* W1 = w1 + (size_t)l * 256 * 256;
    const float* B1 = b1 + (size_t)l * 256;
    const float* W2 = w2 + (size_t)l * 256 * 256;
    const float* B2 = b2 + (size_t)l * 256;
    const float* W3 = w3 + (size_t)l * 256 * 256;
    const float* B3 = b3 + (size_t)l * 256;

    if (tid < 128) act[tid] = rel[((size_t)l * RR + r) * 128 + tid];
    __syncthreads();

    auto layer = [&](const float* w, const float* b, int Kdim,
                     float* src, float* dst, int mode) {
        float acc = b[tid];
        const int T = Kdim >> 4;
        float rg[16];
        #pragma unroll
        for (int p = 0; p < 16; p++)
            rg[p] = __ldg(&w[(size_t)(p * 16 + lj) * Kdim + lk]);
        for (int t = 0; t < T; t++) {
            #pragma unroll
            for (int p = 0; p < 16; p++) wt[lk][p * 16 + lj] = rg[p];
            __syncthreads();
            if (t + 1 < T) {
                int k0 = (t + 1) * 16;
                #pragma unroll
                for (int p = 0; p < 16; p++)
                    rg[p] = __ldg(&w[(size_t)(p * 16 + lj) * Kdim + k0 + lk]);
            }
            int kb = t * 16;
            #pragma unroll
            for (int k = 0; k < 16; k++)
                acc = fmaf(wt[k][tid], src[kb + k], acc);
            __syncthreads();
        }
        if (mode == 0) { dst[tid] = fmaxf(acc, 0.f); __syncthreads(); }
        else {
            size_t o = ((size_t)l * RR + r) * 128;
            if (tid < 128) g_gamma[o + tid] = acc;
            else           g_beta [o + (tid - 128)] = acc;
        }
    };

    layer(W0, B0, 128, act, nxt, 0);
    layer(W1, B1, 256, nxt, act, 0);
    layer(W2, B2, 256, act, nxt, 0);
    layer(W3, B3, 256, nxt, nullptr, 2);
}

// ---------------------------------------------------------------------------
// Common tiling constants
// ---------------------------------------------------------------------------
#define BK 32
#define PITCH 40
#define TILE_B (128 * PITCH * 2)        // 10240 B
#define STAGE_FP (3 * TILE_B)
#define GSMEM_FP (2 * STAGE_FP)         // 61440

// ---------------------------------------------------------------------------
// gemm_fp: 2-term fp16 (A hi/lo fp16, B single fp16).
// OSPLIT: 0 none, 1 fp16 hi/lo.  FP32_OUT: write fp32 C.
// ---------------------------------------------------------------------------
template <bool RELU, int OSPLIT, bool FP32_OUT>
__global__ __launch_bounds__(256) void gemm_fp(
    const __half* __restrict__ Ah, const __half* __restrict__ Al,
    const __half* __restrict__ B,
    const float* __restrict__ bias, float* __restrict__ C,
    __half* __restrict__ Ch, __half* __restrict__ Cl,
    int M, int N, int K)
{
    extern __shared__ char smem[];
    const uint32_t sb = smem_u32(smem);

    const int tid  = threadIdx.x;
    const int wid  = tid >> 5;
    const int lane = tid & 31;
    const int bm0  = blockIdx.x * 128;
    const int bn0  = blockIdx.y * 128;
    const int wm   = (wid & 3) * 32;
    const int wn   = (wid >> 2) * 64;

    float acc[2][8][4];
    #pragma unroll
    for (int mt = 0; mt < 2; mt++)
        #pragma unroll
        for (int nt = 0; nt < 8; nt++)
            #pragma unroll
            for (int q = 0; q < 4; q++) acc[mt][nt][q] = 0.f;

    const __half* gA[2] = {Ah, Al};

    auto prefetch = [&](int stage, int ch) {
        const int k0 = ch * BK;
        const uint32_t base = sb + stage * STAGE_FP;
        #pragma unroll
        for (int hl = 0; hl < 2; hl++)
            #pragma unroll
            for (int it = 0; it < 2; it++) {
                int c = tid + it * 256;
                int row = c >> 2;
                int col8 = (c & 3) << 3;
                uint32_t dst = base + hl * TILE_B + (uint32_t)(row * PITCH + col8) * 2;
                int gr = bm0 + row;
                int ok = (gr < M) ? 16 : 0;
                cpa16(dst, gA[hl] + (size_t)(ok ? gr : 0) * K + k0 + col8, ok);
            }
        #pragma unroll
        for (int it = 0; it < 2; it++) {
            int c = tid + it * 256;
            int row = c >> 2;
            int col8 = (c & 3) << 3;
            uint32_t dst = base + 2 * TILE_B + (uint32_t)(row * PITCH + col8) * 2;
            cpa16(dst, B + (size_t)(bn0 + row) * K + k0 + col8, 16);
        }
        cpa_commit();
    };

    const int a_row = lane & 15;
    const int a_cb  = (lane >> 4) << 3;
    const int b_g   = lane >> 3;
    const int b_r   = lane & 7;
    const int b_row = ((b_g >> 1) << 3) + b_r;
    const int b_cb  = (b_g & 1) << 3;

    const int nchunk = K >> 5;
    prefetch(0, 0);

    for (int ch = 0; ch < nchunk; ch++) {
        const int stage = ch & 1;
        if (ch + 1 < nchunk) { prefetch(stage ^ 1, ch + 1); cpa_wait1(); }
        else                 { cpa_wait0(); }
        __syncthreads();

        const uint32_t base = sb + stage * STAGE_FP;
        #pragma unroll
        for (int ks = 0; ks < 2; ks++) {
            const int kk = ks << 4;
            uint32_t ah[2][4], al[2][4], bh[8][2];
            #pragma unroll
            for (int mt = 0; mt < 2; mt++) {
                uint32_t off = (uint32_t)((wm + mt * 16 + a_row) * PITCH + kk + a_cb) * 2;
                ldsm4(ah[mt], base + off);
                ldsm4(al[mt], base + TILE_B + off);
            }
            #pragma unroll
            for (int nb = 0; nb < 4; nb++) {
                uint32_t off = (uint32_t)((wn + nb * 16 + b_row) * PITCH + kk + b_cb) * 2;
                uint32_t r[4];
                ldsm4(r, base + 2 * TILE_B + off);
                bh[nb*2][0]=r[0]; bh[nb*2][1]=r[1]; bh[nb*2+1][0]=r[2]; bh[nb*2+1][1]=r[3];
            }
            #pragma unroll
            for (int mt = 0; mt < 2; mt++)
                #pragma unroll
                for (int nt = 0; nt < 8; nt++) {
                    mma_f16(acc[mt][nt], ah[mt], bh[nt]);
                    mma_f16(acc[mt][nt], al[mt], bh[nt]);
                }
        }
        __syncthreads();
    }

    const int gid = lane >> 2;
    const int tig = lane & 3;
    #pragma unroll
    for (int nt = 0; nt < 8; nt++) {
        int col = bn0 + wn + nt * 8 + tig * 2;
        float2 bv = *(const float2*)&bias[col];
        #pragma unroll
        for (int mt = 0; mt < 2; mt++) {
            int rr[2] = {bm0 + wm + mt * 16 + gid, bm0 + wm + mt * 16 + gid + 8};
            float2 oo[2];
            oo[0].x = acc[mt][nt][0] + bv.x; oo[0].y = acc[mt][nt][1] + bv.y;
            oo[1].x = acc[mt][nt][2] + bv.x; oo[1].y = acc[mt][nt][3] + bv.y;
            #pragma unroll
            for (int u = 0; u < 2; u++) {
                if (rr[u] >= M) continue;
                float2 o = oo[u];
                if (RELU) { o.x = fmaxf(o.x, 0.f); o.y = fmaxf(o.y, 0.f); }
                if (FP32_OUT) *(float2*)(C + (size_t)rr[u] * N + col) = o;
                if (OSPLIT == 1) {
                    __half h0 = __float2half_rn(o.x);
                    __half h1 = __float2half_rn(o.y);
                    uint32_t hp = ((uint32_t)__half_as_ushort(h1) << 16) | __half_as_ushort(h0);
                    uint32_t lp = pack_h2(o.x - __half2float(h0), o.y - __half2float(h1));
                    *(uint32_t*)(Ch + (size_t)rr[u] * N + col) = hp;
                    *(uint32_t*)(Cl + (size_t)rr[u] * N + col) = lp;
                }
            }
        }
    }
}

// ---------------------------------------------------------------------------
extern "C" void kernel_launch(void* const* d_in, const int* in_sizes, int n_in,
                              void* d_out, int out_size)
{
    const int* edge_index = (const int*)d_in[0];
    const int* edge_type  = (const int*)d_in[1];
    const float* embed_w = (const float*)d_in[2];
    const float* rel_emb = (const float*)d_in[3];
    const float* rmw0 = (const float*)d_in[4];
    const float* rmb0 = (const float*)d_in[5];
    const float* rmw1 = (const float*)d_in[6];
    const float* rmb1 = (const float*)d_in[7];
    const float* rmw2 = (const float*)d_in[8];
    const float* rmb2 = (const float*)d_in[9];
    const float* rmw3 = (const float*)d_in[10];
    const float* rmb3 = (const float*)d_in[11];
    const float* W_w  = (const float*)d_in[12];
    const float* W_b  = (const float*)d_in[13];
    const float* mlp_w0 = (const float*)d_in[14];
    const float* mlp_b0 = (const float*)d_in[15];
    const float* mlp_w1 = (const float*)d_in[16];
    const float* mlp_b1 = (const float*)d_in[17];
    const float* eps    = (const float*)d_in[18];

    const int E = in_sizes[1];
    const int M = in_sizes[2] / DD;

    cudaFuncSetAttribute(gemm_fp<false, 0, true>,
                         cudaFuncAttributeMaxDynamicSharedMemorySize, GSMEM_FP);
    cudaFuncSetAttribute(gemm_fp<true,  1, false>,
                         cudaFuncAttributeMaxDynamicSharedMemorySize, GSMEM_FP);
    cudaFuncSetAttribute(gemm_fp<false, 1, true>,
                         cudaFuncAttributeMaxDynamicSharedMemorySize, GSMEM_FP);

    float *xw, *x1;
    int *cnt, *cur;
    __half *xs_h, *xs_l, *os_h, *os_l, *hs_h, *hs_l, *wwf, *w0f, *w1f;
    cudaGetSymbolAddress((void**)&xw,   g_xw);
    cudaGetSymbolAddress((void**)&x1,   g_x1);
    cudaGetSymbolAddress((void**)&cnt,  g_cnt);
    cudaGetSymbolAddress((void**)&cur,  g_cur);
    cudaGetSymbolAddress((void**)&xs_h, g_xs_hi);
    cudaGetSymbolAddress((void**)&xs_l, g_xs_lo);
    cudaGetSymbolAddress((void**)&os_h, g_osf_hi);
    cudaGetSymbolAddress((void**)&os_l, g_osf_lo);
    cudaGetSymbolAddress((void**)&hs_h, g_hsf_hi);
    cudaGetSymbolAddress((void**)&hs_l, g_hsf_lo);
    cudaGetSymbolAddress((void**)&wwf,  g_wwf);
    cudaGetSymbolAddress((void**)&w0f,  g_w0f);
    cudaGetSymbolAddress((void**)&w1f,  g_w1f);

    const int GB = (M + 127) / 128;

    // prep
    {
        int n8 = M * DD / 8;
        split8h_kernel<<<(n8 + 255)/256, 256>>>(embed_w, xs_h, xs_l, n8);
    }
    hconv_kernel<<<(32768/8 + 255)/256, 256>>>(W_w, wwf, 32768/8);
    wconv_kernel<<<(2*8192 + 255)/256, 256>>>(mlp_w0, mlp_w1, w0f, w1f, 8192);
    film_kernel<<<RR * LL, 256>>>(
        rel_emb, rmw0, rmb0, rmw1, rmb1, rmw2, rmb2, rmw3, rmb3);
    cudaMemsetAsync(cnt, 0, (size_t)(M + 1) * sizeof(int));
    cudaMemsetAsync(cur, 0, (size_t)M * sizeof(int));
    hist_kernel<<<(E + 255) / 256, 256>>>(edge_index, E);
    // gemm1 layer 0
    gemm_fp<false, 0, true><<<dim3(GB, 1), 256, GSMEM_FP>>>(
        xs_h, xs_l, wwf, W_b, xw, nullptr, nullptr, M, 128, 128);
    int nsb = (M + SCAN_E - 1) / SCAN_E;
    scan1_kernel<<<nsb, SCAN_T>>>(M);
    scan23_kernel<<<(M + 255) / 256, 256>>>(M, E);
    scatter_kernel<<<(E + 255) / 256, 256>>>(edge_index, edge_type, E);

    for (int l = 0; l < LL; l++) {
        const float* x_fp32 = (l == 0) ? embed_w : x1;

        if (l > 0) {
            gemm_fp<false, 0, true><<<dim3(GB, 1), 256, GSMEM_FP>>>(
                xs_h, xs_l, wwf + l * 16384,
                W_b + (size_t)l * 128, xw, nullptr, nullptr, M, 128, 128);
        }

        // gather: out = (1+eps)*x + aggr  -> fp16 hi/lo
        gather_kernel<<<(M * 32 + 255) / 256, 256>>>(x_fp32, eps, l, M);

        // gemm2: h = relu(out @ w0^T + b0) -> fp16 hi/lo
        gemm_fp<true, 1, false><<<dim3(GB, 2), 256, GSMEM_FP>>>(
            os_h, os_l, w0f + (size_t)l * 32768,
            mlp_b0 + (size_t)l * 256, nullptr, hs_h, hs_l, M, 256, 128);

        // gemm3: x' = h @ w1^T + b1
        if (l < LL - 1) {
            gemm_fp<false, 1, true><<<dim3(GB, 1), 256, GSMEM_FP>>>(
                hs_h, hs_l, w1f + (size_t)l * 32768,
                mlp_b1 + (size_t)l * 128, x1, xs_h, xs_l, M, 128, 256);
        } else {
            gemm_fp<false, 0, true><<<dim3(GB, 1), 256, GSMEM_FP>>>(
                hs_h, hs_l, w1f + (size_t)l * 32768,
                mlp_b1 + (size_t)l * 128, (float*)d_out, nullptr, nullptr, M, 128, 256);
        }
    }
}